// round 3
// baseline (speedup 1.0000x reference)
#include <cuda_runtime.h>

#define NTH   512
#define NST   32
#define SCAP  (NTH * NST)        // 16384 states capacity
#define TMAX  64
#define CH    256                // cand-history stride (>= 4*T)
#define SPCAP 2048
#define SPT   4                  // sparse entries per thread
#define SENT  (-1e38f)
#define NEGV  (-1e30f)
#define NFMAX 6000

// cand history: per frame, the 4*T values v_t[prev_last[...]] needed to
// recompute argmax during backtrace. 6000*256*4B = 6.1MB scratch.
__device__ float g_hist[NFMAX * CH];

struct SM {
    float vraw[SCAP + 4];        // V = vraw+4; vraw[3] holds v[-1] = NEG
    float lt[TMAX * TMAX];       // log_trans (one beat slice; identical across beats)
    float cand[4 * 64];          // staged cand, layout [b][64]
    float dens[4];               // d0,d1,d2 for current frame
    int   plsm[256];             // prev_last flat (4*T)
    int   slist[SPCAP];          // sparse exception states: (s<<2)|code
    int   scount;
    int   pad0[3];
    unsigned short ptab[SCAP];   // (fidx+1)<<2 | ptrcode  (fidx 0 => not a first state)
    float rv[NTH];               // final argmax partials
    int   ri[NTH];
};

__global__ void __launch_bounds__(NTH, 1)
dbn_viterbi_kernel(const float* __restrict__ acts,
                   const float* __restrict__ log_trans,
                   const int*   __restrict__ prev_last,
                   const int*   __restrict__ first_states,
                   const int*   __restrict__ pointer,
                   float*       __restrict__ out,
                   int S, int T, int NF, int out_size)
{
    extern __shared__ unsigned char smraw[];
    SM* sm = reinterpret_cast<SM*>(smraw);
    float* V = sm->vraw + 4;

    const int tid  = threadIdx.x;
    const int lane = tid & 31;
    const int NT4  = 4 * T;          // number of (beat, tempo) segments (<=256)
    const int s0   = tid * NST;      // this thread's dense state segment

    // ---------------- one-time setup ----------------
    {
        float v0 = -logf((float)S);
        for (int s = tid; s < SCAP; s += NTH) V[s] = v0;
        if (tid == 0) V[-1] = NEGV;
        for (int idx = tid; idx < T * T; idx += NTH) sm->lt[idx] = log_trans[idx];
        for (int idx = tid; idx < 4 * 64; idx += NTH) sm->cand[idx] = 0.f;
        for (int s = tid; s < SCAP; s += NTH)
            sm->ptab[s] = (s < S) ? (unsigned short)(pointer[s] & 3) : (unsigned short)0;
        if (tid < NT4) sm->plsm[tid] = prev_last[tid];
        if (tid == 0) sm->scount = 0;
    }
    __syncthreads();  // lt / ptab-base ready

    // mark first states in ptab (distinct addresses, no race)
    if (tid < NT4) {
        int fs = first_states[tid];
        sm->ptab[fs] = (unsigned short)(sm->ptab[fs] | ((tid + 1) << 2));
    }

    // transition-role setup: lane pair (task, chunk c in {0,1}); i = c*32 + k
    const bool isA = (tid < 2 * NT4);
    int  a_b = 0, a_c = 0, a_faddr = 0;
    bool a_beat0 = false;
    float ltreg[32];
    if (isA) {
        int task = tid >> 1;
        a_c = tid & 1;
        a_b = task / T;
        int a_j = task - a_b * T;
        a_faddr = first_states[task];
        a_beat0 = (a_b == 0);
        #pragma unroll
        for (int k = 0; k < 32; k++) {
            int i = a_c * 32 + k;
            ltreg[k] = (i < T) ? sm->lt[i * T + a_j] : SENT;
        }
    } else {
        #pragma unroll
        for (int k = 0; k < 32; k++) ltreg[k] = SENT;
    }

    // staging role
    int my_pl = 0, my_candoff = 0;
    if (tid < NT4) {
        my_pl = sm->plsm[tid];
        int b = tid / T, i = tid - b * T;
        my_candoff = b * 64 + i;
    }
    __syncthreads();  // first flags in ptab complete

    // sparse exception list: ptr != 0 and not a first state
    {
        for (int k = 0; k < NST; k++) {
            int s = s0 + k;
            if (s < S) {
                unsigned short p = sm->ptab[s];
                if ((p & 3) != 0 && (p >> 2) == 0) {
                    int pos = atomicAdd(&sm->scount, 1);
                    if (pos < SPCAP) sm->slist[pos] = (s << 2) | (p & 3);
                }
            }
        }
    }
    __syncthreads();

    int scount = min(sm->scount, SPCAP);
    int sp_s[SPT]; int sp_c[SPT];
    #pragma unroll
    for (int e = 0; e < SPT; e++) {
        int idx = tid + e * NTH;
        if (idx < scount) { int v = sm->slist[idx]; sp_s[e] = v >> 2; sp_c[e] = v & 3; }
        else              { sp_s[e] = -1;           sp_c[e] = 0; }
    }

    // ---------------- forward Viterbi ----------------
    for (int t = 0; t < NF; t++) {
        __syncthreads();   // barA: v_t complete

        // phase L: loads (reads of v_t only)
        if (tid == 0) {
            float ab = acts[2 * t], ad = acts[2 * t + 1];
            sm->dens[0] = logf((1.f - ab - ad) / 15.f);
            sm->dens[1] = logf(ab);
            sm->dens[2] = logf(ad);
        }
        if (tid < NT4) {
            float c = V[my_pl];
            sm->cand[my_candoff] = c;
            g_hist[t * CH + tid] = c;      // backtrace history
        }
        float r[NST];
        #pragma unroll
        for (int g = 0; g < NST / 4; g++)
            *(float4*)(r + 4 * g) = *(const float4*)(V + s0 + 4 * g);
        float vm1 = V[s0 - 1];
        float sprev[SPT];
        #pragma unroll
        for (int e = 0; e < SPT; e++)
            sprev[e] = (sp_s[e] >= 0) ? V[sp_s[e] - 1] : 0.f;

        __syncthreads();   // bar2: all reads of v_t done; writes may begin
        float d0 = sm->dens[0], d1 = sm->dens[1], d2 = sm->dens[2];

        // dense: v_{t+1}[s] = v_t[s-1] + d0  (exception slots get garbage; fixed below)
        #pragma unroll
        for (int k = NST - 1; k >= 1; k--) r[k] = r[k - 1] + d0;
        r[0] = vm1 + d0;
        #pragma unroll
        for (int g = 0; g < NST / 4; g++)
            *(float4*)(V + s0 + 4 * g) = *(float4*)(r + 4 * g);

        // transition max (registers + cand broadcast; no argmax needed here)
        float acc = SENT;
        if (isA) {
            const float* cb = sm->cand + a_b * 64 + a_c * 32;
            #pragma unroll
            for (int k = 0; k < 32; k++)
                acc = fmaxf(acc, cb[k] + ltreg[k]);
        }

        __syncthreads();   // bar3: dense stores done; fixups now
        float other = __shfl_down_sync(0xffffffffu, acc, 1);
        if (isA && a_c == 0) {
            float best = fmaxf(acc, other);
            V[a_faddr] = best + (a_beat0 ? d2 : d1);
        }
        #pragma unroll
        for (int e = 0; e < SPT; e++)
            if (sp_s[e] >= 0)
                V[sp_s[e]] = sprev[e] + (sp_c[e] == 2 ? d2 : d1);
    }
    __syncthreads();

    // ---------------- final argmax (first occurrence) ----------------
    {
        float bv = SENT; int bi = 0;
        #pragma unroll
        for (int k = 0; k < NST; k++) {
            int s = s0 + k;
            if (s < S) {
                float x = V[s];
                if (x > bv) { bv = x; bi = s; }
            }
        }
        sm->rv[tid] = bv; sm->ri[tid] = bi;
    }
    __syncthreads();

    if (tid < 32) {
        float bv = SENT; int bi = 0x7fffffff;
        for (int m = lane; m < NTH; m += 32) {
            float x = sm->rv[m]; int ii = sm->ri[m];
            if (x > bv || (x == bv && ii < bi)) { bv = x; bi = ii; }
        }
        #pragma unroll
        for (int off = 16; off; off >>= 1) {
            float xv = __shfl_down_sync(0xffffffffu, bv, off);
            int   xi = __shfl_down_sync(0xffffffffu, bi, off);
            if (xv > bv || (xv == bv && xi < bi)) { bv = xv; bi = xi; }
        }
        bi = __shfl_sync(0xffffffffu, bi, 0);
        bv = __shfl_sync(0xffffffffu, bv, 0);
        if (lane == 0) {
            if (out_size > NF) out[NF] = bv;       // logp
            out[NF - 1] = (float)bi;               // path[NF-1]
        }

        // ---------------- backtrace (warp 0) ----------------
        int s = bi, tt = NF - 1;
        while (tt > 0) {
            unsigned short pt = sm->ptab[s];
            int f = pt >> 2;
            if (f) {
                // first state: recompute argmax_i (first occurrence), exact-bit
                f -= 1;
                int b = f / T, j = f - b * T;
                float bvv = SENT; int bii = 0x7fffffff;
                for (int i = lane; i < T; i += 32) {
                    float x = g_hist[tt * CH + b * T + i] + sm->lt[i * T + j];
                    if (x > bvv || (x == bvv && i < bii)) { bvv = x; bii = i; }
                }
                #pragma unroll
                for (int off = 16; off; off >>= 1) {
                    float xv = __shfl_down_sync(0xffffffffu, bvv, off);
                    int   xi = __shfl_down_sync(0xffffffffu, bii, off);
                    if (xv > bvv || (xv == bvv && xi < bii)) { bvv = xv; bii = xi; }
                }
                bii = __shfl_sync(0xffffffffu, bii, 0);
                int p = sm->plsm[b * T + bii];
                if (lane == 0) out[tt - 1] = (float)p;
                s = p; tt -= 1;
            } else {
                // emit a chain run (up to 32 entries at once)
                int ss = s - 1 - lane;
                bool isf = (ss >= 0) ? ((sm->ptab[ss] >> 2) != 0) : true;
                unsigned flags = __ballot_sync(0xffffffffu, isf);
                int cnt = flags ? __ffs(flags) : 32;   // include the first-state entry
                cnt = min(cnt, tt);
                if (lane < cnt) out[tt - 1 - lane] = (float)(s - 1 - lane);
                s -= cnt; tt -= cnt;
            }
        }
    }
}

extern "C" void kernel_launch(void* const* d_in, const int* in_sizes, int n_in,
                              void* d_out, int out_size)
{
    const float* acts = (const float*)d_in[0];
    const float* lt   = (const float*)d_in[1];
    const int*   pl   = (const int*)d_in[2];
    const int*   fs   = (const int*)d_in[3];
    const int*   ptr  = (const int*)d_in[4];

    int NF = in_sizes[0] / 2;          // activations (NF, 2)
    int T  = in_sizes[2] / 4;          // prev_last (4, T)
    int S  = in_sizes[4];              // pointer (S,)
    if (NF > NFMAX) NF = NFMAX;

    size_t smem = sizeof(SM);
    static bool attr_set = false;
    if (!attr_set) {
        cudaFuncSetAttribute(dbn_viterbi_kernel,
                             cudaFuncAttributeMaxDynamicSharedMemorySize, (int)smem);
        attr_set = true;
    }
    dbn_viterbi_kernel<<<1, NTH, smem>>>(acts, lt, pl, fs, ptr,
                                         (float*)d_out, S, T, NF, out_size);
}